// round 15
// baseline (speedup 1.0000x reference)
#include <cuda_runtime.h>
#include <cstdint>
#include <math.h>

#define N_LEVELS 16
#define LOG2_HASHMAP 19
#define TABLE_ROWS (1u << 19)
#define TPB 256
#define PPB 64              // points per block; 4 threads per point, 4 levels each
#define LPT 4               // levels per thread
#define KEY_BITS 18
#define NBINS (1 << KEY_BITS)   // 18-bit morton buckets (6 bits/axis, 64^3)
#define NCHUNK (NBINS / 1024)   // 256 scan chunks
#define MAXPTS 1000000

// zero-initialized at module load; scan1 re-zeros after reading each replay
__device__ unsigned g_hist[NBINS];
__device__ unsigned g_off[NBINS];    // exclusive prefix WITHIN 1024-bin chunk
__device__ unsigned g_bsum[NCHUNK];  // per-chunk totals (scanned inside scatter)
__device__ unsigned g_key[MAXPTS];   // packed: (rank_in_bin << KEY_BITS) | morton_key
__device__ int      g_sidx[MAXPTS];

struct LevelParams {
    float res[N_LEVELS];
    unsigned int hs[N_LEVELS];
    unsigned long long magic[N_LEVELS];
};

__device__ __forceinline__ unsigned mod_hs(unsigned h, unsigned hs, unsigned long long M) {
    unsigned q = (unsigned)__umul64hi((unsigned long long)h, M);
    return h - q * hs;
}

// spread low bits with 2-bit gaps (enough for 6 bits)
__device__ __forceinline__ unsigned part1by2(unsigned v) {
    v &= 0x3FFu;
    v = (v | (v << 16)) & 0x030000FFu;
    v = (v | (v << 8))  & 0x0300F00Fu;
    v = (v | (v << 4))  & 0x030C30C3u;
    v = (v | (v << 2))  & 0x09249249u;
    return v;
}
__device__ __forceinline__ unsigned morton_key(float px, float py, float pz) {
    unsigned ix = min(63u, (unsigned)(px * 64.f));
    unsigned iy = min(63u, (unsigned)(py * 64.f));
    unsigned iz = min(63u, (unsigned)(pz * 64.f));
    return part1by2(ix) | (part1by2(iy) << 1) | (part1by2(iz) << 2);
}

// histogram; atomicAdd's return value IS this point's rank within its bin
__global__ void hist_kernel(const float* __restrict__ x, int n) {
    int i = blockIdx.x * blockDim.x + threadIdx.x;
    if (i < n) {
        size_t b = 3ull * (size_t)i;
        unsigned k = morton_key(x[b], x[b + 1], x[b + 2]);
        unsigned rank = atomicAdd(&g_hist[k], 1u);
        g_key[i] = (rank << KEY_BITS) | k;
    }
}

// level-1 scan: each block scans its 1024-bin chunk in smem,
// and re-zeros g_hist for the next graph replay (replaces zero_hist kernel).
__global__ __launch_bounds__(1024) void scan1_kernel() {
    __shared__ unsigned sh[1024];
    int t = threadIdx.x;
    int base = blockIdx.x * 1024;
    unsigned v = g_hist[base + t];
    g_hist[base + t] = 0u;                  // ready for next launch
    sh[t] = v;
    __syncthreads();
    for (int off = 1; off < 1024; off <<= 1) {
        unsigned u = (t >= off) ? sh[t - off] : 0u;
        __syncthreads();
        sh[t] += u;
        __syncthreads();
    }
    g_off[base + t] = sh[t] - v;            // exclusive within chunk
    if (t == 1023) g_bsum[blockIdx.x] = sh[t];
}

// atomic-free scatter; each block scans the 256 chunk totals in smem
// (replaces the separate scan2 kernel launch)
__global__ __launch_bounds__(256) void scatter_kernel(int n) {
    __shared__ unsigned sh[NCHUNK];
    __shared__ unsigned bpre[NCHUNK];
    int t = threadIdx.x;
    unsigned v = g_bsum[t];                 // NCHUNK == blockDim == 256
    sh[t] = v;
    __syncthreads();
    #pragma unroll
    for (int off = 1; off < NCHUNK; off <<= 1) {
        unsigned u = (t >= off) ? sh[t - off] : 0u;
        __syncthreads();
        sh[t] += u;
        __syncthreads();
    }
    bpre[t] = sh[t] - v;                    // exclusive chunk prefix
    __syncthreads();

    int i = blockIdx.x * blockDim.x + t;
    if (i < n) {
        unsigned pk   = g_key[i];
        unsigned k    = pk & (NBINS - 1u);
        unsigned rank = pk >> KEY_BITS;
        __stcs(&g_sidx[g_off[k] + bpre[k >> 10] + rank], i);  // streaming: read once later
    }
}

__global__ __launch_bounds__(TPB, 8) void hashgrid_kernel(
    const float* __restrict__ x,
    const float* __restrict__ tables,
    float* __restrict__ out,
    int n, LevelParams P)
{
    __shared__ float s[PPB * 35];
    __shared__ float sx[PPB * 3];
    __shared__ int   sidx[PPB];
    int tid = threadIdx.x;
    int p   = tid & (PPB - 1);   // point within block
    int h   = tid >> 6;          // quarter of levels: 0..3

    if (tid < PPB) {
        int gp = blockIdx.x * PPB + tid;
        int si = (gp < n) ? g_sidx[gp] : -1;
        sidx[tid] = si;
        float a = 0.f, bb = 0.f, c = 0.f;
        if (si >= 0) {
            size_t bo = 3ull * (size_t)si;
            a = x[bo]; bb = x[bo + 1]; c = x[bo + 2];
        }
        sx[tid * 3 + 0] = a; sx[tid * 3 + 1] = bb; sx[tid * 3 + 2] = c;
    }
    __syncthreads();

    float px = sx[p * 3], py = sx[p * 3 + 1], pz = sx[p * 3 + 2];
    float* row = s + p * 35;
    if (h == 0) { row[0] = px; row[1] = py; row[2] = pz; }

    const unsigned PR1 = 2654435761u, PR2 = 805459861u;

    #pragma unroll
    for (int k = 0; k < LPT; ++k) {
        int l = h + 4 * k;
        float r = P.res[l];
        float xs0 = px * r, xs1 = py * r, xs2 = pz * r;
        int i0 = (int)xs0, i1 = (int)xs1, i2 = (int)xs2;
        float f0 = xs0 - (float)i0;
        float f1 = xs1 - (float)i1;
        float f2 = xs2 - (float)i2;

        float wx0 = 1.f - f0;
        float wy0 = 1.f - f1;
        float wz0 = 1.f - f2;

        unsigned a0 = (unsigned)i0;
        unsigned b0 = (unsigned)i1 * PR1;
        unsigned c0 = (unsigned)i2 * PR2;

        const float2* tbl  = (const float2*)tables + (size_t)l * TABLE_ROWS;
        const float4* tbl4 = (const float4*)tbl;
        unsigned hs = P.hs[l];
        unsigned long long M = P.magic[l];

        bool odd = (i0 & 1) != 0;

        float acc0 = 0.f, acc1 = 0.f;

        // one (cy,cz) pair per step: minimal live state -> low reg pressure
        #pragma unroll
        for (int q = 0; q < 4; ++q) {
            unsigned bq = (q & 1) ? (b0 + PR1) : b0;
            unsigned cq = (q & 2) ? (c0 + PR2) : c0;
            unsigned bcq = bq ^ cq;
            unsigned h0 = mod_hs(a0 ^ bcq, hs, M);
            float4 v = __ldg(tbl4 + (h0 >> 1));
            float2 e;
            if (odd) e = __ldg(tbl + mod_hs((a0 + 1u) ^ bcq, hs, M));

            bool lo = (h0 & 1u) == 0u;
            float t0x = lo ? v.x : v.z, t0y = lo ? v.y : v.w;
            float t1x, t1y;
            if (odd) { t1x = e.x; t1y = e.y; }
            else     { t1x = lo ? v.z : v.x; t1y = lo ? v.w : v.y; }

            float wyz = ((q & 1) ? f1 : wy0) * ((q & 2) ? f2 : wz0);
            float w0 = wx0 * wyz;
            float w1 = f0  * wyz;
            acc0 = fmaf(t0x, w0, fmaf(t1x, w1, acc0));
            acc1 = fmaf(t0y, w0, fmaf(t1y, w1, acc1));
        }
        row[3 + 2 * l]     = acc0;
        row[3 + 2 * l + 1] = acc1;
    }

    __syncthreads();

    // scattered write-out: one warp per point-row, contiguous 140B per row.
    // Streaming stores: output is never re-read; keep it from evicting the
    // L2-resident hash tables (which see ~50 touches per sector).
    int warp = tid >> 5, lane = tid & 31;
    for (int rr = warp; rr < PPB; rr += TPB / 32) {
        int si = sidx[rr];
        if (si < 0) continue;
        size_t base = (size_t)si * 35;
        const float* srow = s + rr * 35;
        #pragma unroll
        for (int e = lane; e < 35; e += 32)
            __stcs(&out[base + e], srow[e]);
    }
}

extern "C" void kernel_launch(void* const* d_in, const int* in_sizes, int n_in,
                              void* d_out, int out_size)
{
    const float* x      = (const float*)d_in[0];
    const float* tables = (const float*)d_in[1];
    float* out          = (float*)d_out;
    int n = in_sizes[0] / 3;

    LevelParams P;
    double beta = exp((log(2048.0) - log(16.0)) / 15.0);
    for (int l = 0; l < N_LEVELS; ++l) {
        double rr = floor(16.0 * pow(beta, (double)l));
        P.res[l] = (float)rr;
        unsigned long long r3 = (unsigned long long)rr;
        r3 = r3 * r3 * r3;
        unsigned long long cap = 1ull << LOG2_HASHMAP;
        unsigned hs = (unsigned)((r3 < cap) ? r3 : cap);
        P.hs[l]    = hs;
        P.magic[l] = (~0ull) / (unsigned long long)hs + 1ull;
    }

    int pblocks = (n + 255) / 256;
    hist_kernel<<<pblocks, 256>>>(x, n);
    scan1_kernel<<<NCHUNK, 1024>>>();
    scatter_kernel<<<pblocks, 256>>>(n);

    int blocks = (n + PPB - 1) / PPB;
    hashgrid_kernel<<<blocks, TPB>>>(x, tables, out, n, P);
}

// round 16
// speedup vs baseline: 1.0059x; 1.0059x over previous
#include <cuda_runtime.h>
#include <cstdint>
#include <math.h>

#define N_LEVELS 16
#define LOG2_HASHMAP 19
#define TABLE_ROWS (1u << 19)
#define TPB 256
#define PPB 64              // points per block; 4 threads per point, 4 levels each
#define LPT 4               // levels per thread
#define KEY_BITS 18
#define NBINS (1 << KEY_BITS)   // 18-bit morton buckets (6 bits/axis, 64^3)
#define NCHUNK (NBINS / 1024)   // 256 scan chunks
#define MAXPTS 1000000

// zero-initialized at module load; scan1 re-zeros after reading each replay
__device__ unsigned g_hist[NBINS];
__device__ unsigned g_off[NBINS];    // exclusive prefix WITHIN 1024-bin chunk
__device__ unsigned g_bsum[NCHUNK];  // per-chunk totals (scanned inside scatter)
__device__ unsigned g_key[MAXPTS];   // packed: (rank_in_bin << KEY_BITS) | morton_key
__device__ int      g_sidx[MAXPTS];

struct LevelParams {
    float res[N_LEVELS];
    unsigned int hs[N_LEVELS];
    unsigned long long magic[N_LEVELS];
};

__device__ __forceinline__ unsigned mod_hs(unsigned h, unsigned hs, unsigned long long M) {
    unsigned q = (unsigned)__umul64hi((unsigned long long)h, M);
    return h - q * hs;
}

// spread low bits with 2-bit gaps (enough for 6 bits)
__device__ __forceinline__ unsigned part1by2(unsigned v) {
    v &= 0x3FFu;
    v = (v | (v << 16)) & 0x030000FFu;
    v = (v | (v << 8))  & 0x0300F00Fu;
    v = (v | (v << 4))  & 0x030C30C3u;
    v = (v | (v << 2))  & 0x09249249u;
    return v;
}
__device__ __forceinline__ unsigned morton_key(float px, float py, float pz) {
    unsigned ix = min(63u, (unsigned)(px * 64.f));
    unsigned iy = min(63u, (unsigned)(py * 64.f));
    unsigned iz = min(63u, (unsigned)(pz * 64.f));
    return part1by2(ix) | (part1by2(iy) << 1) | (part1by2(iz) << 2);
}

// histogram; atomicAdd's return value IS this point's rank within its bin
__global__ void hist_kernel(const float* __restrict__ x, int n) {
    int i = blockIdx.x * blockDim.x + threadIdx.x;
    if (i < n) {
        size_t b = 3ull * (size_t)i;
        unsigned k = morton_key(x[b], x[b + 1], x[b + 2]);
        unsigned rank = atomicAdd(&g_hist[k], 1u);
        g_key[i] = (rank << KEY_BITS) | k;
    }
}

// level-1 scan: each block scans its 1024-bin chunk in smem,
// and re-zeros g_hist for the next graph replay (replaces zero_hist kernel).
__global__ __launch_bounds__(1024) void scan1_kernel() {
    __shared__ unsigned sh[1024];
    int t = threadIdx.x;
    int base = blockIdx.x * 1024;
    unsigned v = g_hist[base + t];
    g_hist[base + t] = 0u;                  // ready for next launch
    sh[t] = v;
    __syncthreads();
    for (int off = 1; off < 1024; off <<= 1) {
        unsigned u = (t >= off) ? sh[t - off] : 0u;
        __syncthreads();
        sh[t] += u;
        __syncthreads();
    }
    g_off[base + t] = sh[t] - v;            // exclusive within chunk
    if (t == 1023) g_bsum[blockIdx.x] = sh[t];
}

// atomic-free scatter; each block scans the 256 chunk totals in smem
// (replaces the separate scan2 kernel launch)
__global__ __launch_bounds__(256) void scatter_kernel(int n) {
    __shared__ unsigned sh[NCHUNK];
    __shared__ unsigned bpre[NCHUNK];
    int t = threadIdx.x;
    unsigned v = g_bsum[t];                 // NCHUNK == blockDim == 256
    sh[t] = v;
    __syncthreads();
    #pragma unroll
    for (int off = 1; off < NCHUNK; off <<= 1) {
        unsigned u = (t >= off) ? sh[t - off] : 0u;
        __syncthreads();
        sh[t] += u;
        __syncthreads();
    }
    bpre[t] = sh[t] - v;                    // exclusive chunk prefix
    __syncthreads();

    int i = blockIdx.x * blockDim.x + t;
    if (i < n) {
        unsigned pk   = g_key[i];
        unsigned k    = pk & (NBINS - 1u);
        unsigned rank = pk >> KEY_BITS;
        g_sidx[g_off[k] + bpre[k >> 10] + rank] = i;
    }
}

__global__ __launch_bounds__(TPB, 8) void hashgrid_kernel(
    const float* __restrict__ x,
    const float* __restrict__ tables,
    float* __restrict__ out,
    int n, LevelParams P)
{
    __shared__ float s[PPB * 35];
    __shared__ float sx[PPB * 3];
    __shared__ int   sidx[PPB];
    int tid = threadIdx.x;
    int p   = tid & (PPB - 1);   // point within block
    int h   = tid >> 6;          // quarter of levels: 0..3

    if (tid < PPB) {
        int gp = blockIdx.x * PPB + tid;
        int si = (gp < n) ? g_sidx[gp] : -1;
        sidx[tid] = si;
        float a = 0.f, bb = 0.f, c = 0.f;
        if (si >= 0) {
            size_t bo = 3ull * (size_t)si;
            a = x[bo]; bb = x[bo + 1]; c = x[bo + 2];
        }
        sx[tid * 3 + 0] = a; sx[tid * 3 + 1] = bb; sx[tid * 3 + 2] = c;
    }
    __syncthreads();

    float px = sx[p * 3], py = sx[p * 3 + 1], pz = sx[p * 3 + 2];
    float* row = s + p * 35;
    if (h == 0) { row[0] = px; row[1] = py; row[2] = pz; }

    const unsigned PR1 = 2654435761u, PR2 = 805459861u;

    #pragma unroll
    for (int k = 0; k < LPT; ++k) {
        int l = h + 4 * k;
        float r = P.res[l];
        float xs0 = px * r, xs1 = py * r, xs2 = pz * r;
        int i0 = (int)xs0, i1 = (int)xs1, i2 = (int)xs2;
        float f0 = xs0 - (float)i0;
        float f1 = xs1 - (float)i1;
        float f2 = xs2 - (float)i2;

        float wx0 = 1.f - f0;
        float wy0 = 1.f - f1;
        float wz0 = 1.f - f2;

        unsigned a0 = (unsigned)i0;
        unsigned b0 = (unsigned)i1 * PR1;
        unsigned c0 = (unsigned)i2 * PR2;

        const float2* tbl  = (const float2*)tables + (size_t)l * TABLE_ROWS;
        const float4* tbl4 = (const float4*)tbl;
        unsigned hs = P.hs[l];
        unsigned long long M = P.magic[l];

        bool odd = (i0 & 1) != 0;

        float acc0 = 0.f, acc1 = 0.f;

        // one (cy,cz) pair per step: minimal live state -> low reg pressure.
        // x-corner pair collapses to ONE aligned float4 when i0 is even
        // (hash prime for x is 1 and every hashmap_size is even -> hid1 = hid0^1).
        #pragma unroll
        for (int q = 0; q < 4; ++q) {
            unsigned bq = (q & 1) ? (b0 + PR1) : b0;
            unsigned cq = (q & 2) ? (c0 + PR2) : c0;
            unsigned bcq = bq ^ cq;
            unsigned h0 = mod_hs(a0 ^ bcq, hs, M);
            float4 v = __ldg(tbl4 + (h0 >> 1));
            float2 e;
            if (odd) e = __ldg(tbl + mod_hs((a0 + 1u) ^ bcq, hs, M));

            bool lo = (h0 & 1u) == 0u;
            float t0x = lo ? v.x : v.z, t0y = lo ? v.y : v.w;
            float t1x, t1y;
            if (odd) { t1x = e.x; t1y = e.y; }
            else     { t1x = lo ? v.z : v.x; t1y = lo ? v.w : v.y; }

            float wyz = ((q & 1) ? f1 : wy0) * ((q & 2) ? f2 : wz0);
            float w0 = wx0 * wyz;
            float w1 = f0  * wyz;
            acc0 = fmaf(t0x, w0, fmaf(t1x, w1, acc0));
            acc1 = fmaf(t0y, w0, fmaf(t1y, w1, acc1));
        }
        row[3 + 2 * l]     = acc0;
        row[3 + 2 * l + 1] = acc1;
    }

    __syncthreads();

    // scattered write-out: one warp per point-row, contiguous 140B per row
    int warp = tid >> 5, lane = tid & 31;
    for (int rr = warp; rr < PPB; rr += TPB / 32) {
        int si = sidx[rr];
        if (si < 0) continue;
        size_t base = (size_t)si * 35;
        const float* srow = s + rr * 35;
        #pragma unroll
        for (int e = lane; e < 35; e += 32)
            out[base + e] = srow[e];
    }
}

extern "C" void kernel_launch(void* const* d_in, const int* in_sizes, int n_in,
                              void* d_out, int out_size)
{
    const float* x      = (const float*)d_in[0];
    const float* tables = (const float*)d_in[1];
    float* out          = (float*)d_out;
    int n = in_sizes[0] / 3;

    // Level params: identical double-precision formula as the reference.
    LevelParams P;
    double beta = exp((log(2048.0) - log(16.0)) / 15.0);
    for (int l = 0; l < N_LEVELS; ++l) {
        double rr = floor(16.0 * pow(beta, (double)l));
        P.res[l] = (float)rr;
        unsigned long long r3 = (unsigned long long)rr;
        r3 = r3 * r3 * r3;
        unsigned long long cap = 1ull << LOG2_HASHMAP;
        unsigned hs = (unsigned)((r3 < cap) ? r3 : cap);
        P.hs[l]    = hs;
        P.magic[l] = (~0ull) / (unsigned long long)hs + 1ull;  // exact for pow2 too
    }

    int pblocks = (n + 255) / 256;
    hist_kernel<<<pblocks, 256>>>(x, n);
    scan1_kernel<<<NCHUNK, 1024>>>();
    scatter_kernel<<<pblocks, 256>>>(n);

    int blocks = (n + PPB - 1) / PPB;
    hashgrid_kernel<<<blocks, TPB>>>(x, tables, out, n, P);
}